// round 3
// baseline (speedup 1.0000x reference)
#include <cuda_runtime.h>
#include <cuda_fp16.h>
#include <math.h>

#define CTAS     128
#define NTHREADS 256
#define TSTEPS   512
#define NBATCH   64
#define HID      1024
#define EMB      512

// ---------------- device scratch (static, no allocation) ----------------
__device__ __half g_X16[(size_t)TSTEPS * NBATCH * EMB];             // 32 MB
__device__ __half g_xproj[(size_t)TSTEPS * CTAS * NBATCH * 32];     // 256 MB
__device__ __half g_hbuf[2][NBATCH * HID];                          // double-buffered h
__device__ unsigned g_bar_count;
__device__ volatile unsigned g_bar_phase;

struct Params {
    const float* Wx[4];   // i,f,g,o : [EMB][HID]
    const float* Wh[4];   // i,f,g,o : [HID][HID]
    const float* b[4];    // i,f,g,o : [HID]
    float* out;           // [T][B][HID]
};

// ---------------- smem layout (bytes) ----------------
#define OFF_WF    0                      // B-fragments (Wx: 32KB, Wh: 64KB)
#define SZ_WF     65536
#define OFF_GATES (OFF_WF + SZ_WF)       // [64][34] fp32
#define SZ_GATES  (64 * 34 * 4)
#define OFF_XP    (OFF_GATES + SZ_GATES) // [64][32] fp16
#define SZ_XP     4096
#define OFF_BIAS  (OFF_XP + SZ_XP)       // [32] fp32
#define SZ_BIAS   128
#define OFF_ABUF  (OFF_BIAS + SZ_BIAS)   // A tile: 64 rows x 1032 halves (padded)
#define SZ_ABUF   (64 * 1032 * 2)
#define SMEM_TOTAL (OFF_ABUF + SZ_ABUF)  // 210560 bytes
#define A_STRIDE  1032                   // halves per row (2064 B; row-to-row bank shift avoids ldmatrix conflicts)

// ---------------- PTX helpers ----------------
__device__ __forceinline__ unsigned su32(const void* p) {
    return (unsigned)__cvta_generic_to_shared(p);
}
__device__ __forceinline__ void cp16(unsigned s, const void* g) {
    asm volatile("cp.async.cg.shared.global [%0], [%1], 16;\n" :: "r"(s), "l"(g));
}
__device__ __forceinline__ void cp_commit() { asm volatile("cp.async.commit_group;\n"); }
template<int N> __device__ __forceinline__ void cp_wait() {
    asm volatile("cp.async.wait_group %0;\n" :: "n"(N));
}
__device__ __forceinline__ void ldmx4(unsigned r[4], unsigned addr) {
    asm volatile("ldmatrix.sync.aligned.m8n8.x4.shared.b16 {%0,%1,%2,%3}, [%4];\n"
                 : "=r"(r[0]), "=r"(r[1]), "=r"(r[2]), "=r"(r[3]) : "r"(addr));
}
__device__ __forceinline__ void hmma(float acc[4], const unsigned a[4], unsigned b0, unsigned b1) {
    asm volatile("mma.sync.aligned.m16n8k16.row.col.f32.f16.f16.f32 "
                 "{%0,%1,%2,%3},{%4,%5,%6,%7},{%8,%9},{%0,%1,%2,%3};\n"
                 : "+f"(acc[0]), "+f"(acc[1]), "+f"(acc[2]), "+f"(acc[3])
                 : "r"(a[0]), "r"(a[1]), "r"(a[2]), "r"(a[3]), "r"(b0), "r"(b1));
}
__device__ __forceinline__ float sigf(float x) { return 1.0f / (1.0f + expf(-x)); }

// Pre-pack W[k][n] (fp32, stride HID) into per-lane mma B-fragments (fp16) in SMEM.
// Fragment for lane L (t4=L&3, gid=L>>2), gate g, kstep ks:
//   b0 = {W[16ks+2*t4][n], W[16ks+2*t4+1][n]},  b1 = same with k+8,  n = hid0+gid
__device__ void prep_frags(uint2* dst, int nk, const float* const W[4], int hid0, int tid) {
    int total = 4 * nk * 32;
    for (int e = tid; e < total; e += NTHREADS) {
        int L  = e & 31;
        int ks = (e >> 5) % nk;
        int g  = e / (nk * 32);
        int t4 = L & 3, gid = L >> 2;
        const float* Wg = W[g];
        int k0 = ks * 16 + 2 * t4;
        int n  = hid0 + gid;
        __half2 lo = __floats2half2_rn(Wg[(k0    ) * HID + n], Wg[(k0 + 1) * HID + n]);
        __half2 hi = __floats2half2_rn(Wg[(k0 + 8) * HID + n], Wg[(k0 + 9) * HID + n]);
        unsigned ulo = *reinterpret_cast<unsigned*>(&lo);
        unsigned uhi = *reinterpret_cast<unsigned*>(&hi);
        dst[e] = make_uint2(ulo, uhi);
    }
}

// Run CNT k-steps of mma for this warp's 2 gate tiles.
template<int CNT>
__device__ __forceinline__ void mma_run(float acc[2][4], unsigned a_lane,
                                        const uint2* b0p, const uint2* b1p, int ks0) {
#pragma unroll
    for (int i = 0; i < CNT; i++) {
        int ks = ks0 + i;
        unsigned a[4];
        ldmx4(a, a_lane + (unsigned)ks * 32u);   // 16 halves = 32 B per kstep
        uint2 q0 = b0p[ks * 32];
        uint2 q1 = b1p[ks * 32];
        hmma(acc[0], a, q0.x, q0.y);
        hmma(acc[1], a, q1.x, q1.y);
    }
}

__device__ __forceinline__ void grid_barrier(unsigned target) {
    __threadfence();            // make this thread's global writes GPU-visible
    __syncthreads();
    if (threadIdx.x == 0) {
        unsigned prev = atomicAdd(&g_bar_count, 1u);
        if (prev == CTAS - 1) {
            g_bar_count = 0;
            __threadfence();
            g_bar_phase = target;
        } else {
            while (g_bar_phase < target) { }
        }
        __threadfence();
    }
    __syncthreads();
}

// ---------------- setup / convert kernels ----------------
__global__ void setup_kernel() {
    int tid = threadIdx.x;
    if (tid == 0) { g_bar_count = 0; g_bar_phase = 0; }
    uint4* p = reinterpret_cast<uint4*>(g_hbuf);
    for (int i = tid; i < (2 * NBATCH * HID * 2) / 16; i += NTHREADS)
        p[i] = make_uint4(0, 0, 0, 0);
}

__global__ void convX_kernel(const float* __restrict__ in) {
    int i = blockIdx.x * blockDim.x + threadIdx.x;   // handles 4 floats
    float4 v = reinterpret_cast<const float4*>(in)[i];
    __half2 a = __floats2half2_rn(v.x, v.y);
    __half2 b = __floats2half2_rn(v.z, v.w);
    reinterpret_cast<uint2*>(g_X16)[i] =
        make_uint2(*reinterpret_cast<unsigned*>(&a), *reinterpret_cast<unsigned*>(&b));
}

// ---------------- persistent LSTM kernel ----------------
__global__ void __launch_bounds__(NTHREADS, 1) lstm_kernel(Params P) {
    extern __shared__ char smem[];
    uint2* wfrag   = reinterpret_cast<uint2*>(smem + OFF_WF);
    float* gates   = reinterpret_cast<float*>(smem + OFF_GATES);
    __half* xp     = reinterpret_cast<__half*>(smem + OFF_XP);
    float* bias_sm = reinterpret_cast<float*>(smem + OFF_BIAS);
    char*  abuf    = smem + OFF_ABUF;

    const int cta  = blockIdx.x;
    const int tid  = threadIdx.x;
    const int w    = tid >> 5;
    const int L    = tid & 31;
    const int hid0 = cta * 8;

    const unsigned abuf_u32 = su32(abuf);
    const unsigned xp_u32   = su32(xp);

    // warp tiling: m-tile = w&3 (16 batch rows), gate-pair = w>>2 ({i,f} or {g,o})
    const int m0 = (w & 3) * 16;
    const int gp = (w >> 2) * 2;
    const unsigned a_lane =
        abuf_u32 + (unsigned)(((m0 + ((L >> 3) & 1) * 8 + (L & 7)) * A_STRIDE + ((L >> 4) * 8)) * 2);

    // biases for this CTA's 32 gate-columns (col = g*8 + j)
    if (tid < 32) {
        const float* bp = P.b[tid >> 3];
        bias_sm[tid] = bp[hid0 + (tid & 7)];
    }

    // ================= PHASE A: input projection =================
    prep_frags(wfrag, 32, P.Wx, hid0, tid);
    __syncthreads();

    const uint2* xb0 = wfrag + (size_t)(gp    ) * 32 * 32 + L;
    const uint2* xb1 = wfrag + (size_t)(gp + 1) * 32 * 32 + L;

    for (int t = 0; t < TSTEPS; t++) {
        // load X tile: 64 rows x 512 halves (1024 B/row = 64 chunks of 16 B)
        // 64*64 = 4096 chunks -> 16 per thread
#pragma unroll
        for (int jj = 0; jj < 16; jj++) {
            int c = tid + jj * NTHREADS;
            int row = c >> 6, col = c & 63;
            cp16(abuf_u32 + row * (A_STRIDE * 2) + col * 16,
                 (const char*)g_X16 + ((size_t)(t * 64 + row) * EMB) * 2 + col * 16);
        }
        cp_commit();
        cp_wait<0>();
        __syncthreads();

        float acc[2][4] = {{0,0,0,0},{0,0,0,0}};
        mma_run<32>(acc, a_lane, xb0, xb1, 0);

        // fragments -> gates smem
        {
            int gid = L >> 2, t4 = L & 3;
#pragma unroll
            for (int s = 0; s < 2; s++) {
                int colb = (gp + s) * 8 + 2 * t4;
                *reinterpret_cast<float2*>(&gates[(m0 + gid    ) * 34 + colb]) = make_float2(acc[s][0], acc[s][1]);
                *reinterpret_cast<float2*>(&gates[(m0 + gid + 8) * 34 + colb]) = make_float2(acc[s][2], acc[s][3]);
            }
        }
        __syncthreads();

        // bias add, fp16 pack, store to g_xproj[t][cta][b][32]
        {
            int row = tid >> 2, cg = tid & 3;
            float v[8];
#pragma unroll
            for (int i = 0; i < 8; i++)
                v[i] = gates[row * 34 + cg * 8 + i] + bias_sm[cg * 8 + i];
            __half2 h0 = __floats2half2_rn(v[0], v[1]);
            __half2 h1 = __floats2half2_rn(v[2], v[3]);
            __half2 h2 = __floats2half2_rn(v[4], v[5]);
            __half2 h3 = __floats2half2_rn(v[6], v[7]);
            uint4 pk = make_uint4(*reinterpret_cast<unsigned*>(&h0), *reinterpret_cast<unsigned*>(&h1),
                                  *reinterpret_cast<unsigned*>(&h2), *reinterpret_cast<unsigned*>(&h3));
            size_t off = (((size_t)t * CTAS + cta) * NBATCH + row) * 32 + cg * 8;
            *reinterpret_cast<uint4*>(&g_xproj[off]) = pk;
        }
        __syncthreads();
    }

    // ================= PHASE B: recurrence =================
    __syncthreads();
    prep_frags(wfrag, 64, P.Wh, hid0, tid);
    __syncthreads();

    const uint2* hb0 = wfrag + (size_t)(gp    ) * 64 * 32 + L;
    const uint2* hb1 = wfrag + (size_t)(gp + 1) * 64 * 32 + L;

    float creg[2] = {0.0f, 0.0f};
    const int e_base = tid * 2;
    const int e_row  = e_base >> 3;
    const int e_j    = e_base & 7;

    for (int t = 0; t < TSTEPS; t++) {
        const __half* hsrc = g_hbuf[t & 1];

        // issue h load in 4 K-quarter groups
        // (each quarter: 64 rows x 32 chunks of 16 B = 2048 chunks -> 8 per thread)
#pragma unroll
        for (int kq = 0; kq < 4; kq++) {
#pragma unroll
            for (int jj = 0; jj < 8; jj++) {
                int c = tid + jj * NTHREADS;
                int row = c >> 5;
                int col = (kq << 5) + (c & 31);
                cp16(abuf_u32 + row * (A_STRIDE * 2) + col * 16,
                     (const char*)hsrc + row * (HID * 2) + col * 16);
            }
            cp_commit();
        }
        // xproj tile (group 5): 4096 B, one 16B chunk per thread
        cp16(xp_u32 + tid * 16,
             (const char*)&g_xproj[(((size_t)t * CTAS + cta) * NBATCH) * 32] + tid * 16);
        cp_commit();

        float acc[2][4] = {{0,0,0,0},{0,0,0,0}};
        cp_wait<4>(); __syncthreads(); mma_run<16>(acc, a_lane, hb0, hb1, 0);
        cp_wait<3>(); __syncthreads(); mma_run<16>(acc, a_lane, hb0, hb1, 16);
        cp_wait<2>(); __syncthreads(); mma_run<16>(acc, a_lane, hb0, hb1, 32);
        cp_wait<1>(); __syncthreads(); mma_run<16>(acc, a_lane, hb0, hb1, 48);

        // fragments -> gates smem
        {
            int gid = L >> 2, t4 = L & 3;
#pragma unroll
            for (int s = 0; s < 2; s++) {
                int colb = (gp + s) * 8 + 2 * t4;
                *reinterpret_cast<float2*>(&gates[(m0 + gid    ) * 34 + colb]) = make_float2(acc[s][0], acc[s][1]);
                *reinterpret_cast<float2*>(&gates[(m0 + gid + 8) * 34 + colb]) = make_float2(acc[s][2], acc[s][3]);
            }
        }
        cp_wait<0>();
        __syncthreads();

        // elementwise LSTM cell: this thread owns (row=e_row, j=e_j) and (e_row, e_j+1)
        __half* hdst = g_hbuf[(t + 1) & 1];
#pragma unroll
        for (int u = 0; u < 2; u++) {
            int jj = e_j + u;
            float zi = gates[e_row * 34 +       jj] + __half2float(xp[e_row * 32 +       jj]);
            float zf = gates[e_row * 34 +  8 +  jj] + __half2float(xp[e_row * 32 +  8 +  jj]);
            float zg = gates[e_row * 34 + 16 +  jj] + __half2float(xp[e_row * 32 + 16 +  jj]);
            float zo = gates[e_row * 34 + 24 +  jj] + __half2float(xp[e_row * 32 + 24 +  jj]);
            float it = sigf(zi);
            float ft = sigf(zf);
            float gt = tanhf(zg);
            float ot = sigf(zo);
            float cn = gt * it + creg[u] * ft;
            creg[u] = cn;
            float hn = tanhf(cn) * ot;
            hdst[e_row * HID + hid0 + jj] = __float2half(hn);
            P.out[((size_t)(t * NBATCH + e_row)) * HID + hid0 + jj] = hn;
        }

        grid_barrier((unsigned)(t + 1));
    }
}

// ---------------- launcher ----------------
extern "C" void kernel_launch(void* const* d_in, const int* in_sizes, int n_in,
                              void* d_out, int out_size) {
    (void)in_sizes; (void)n_in; (void)out_size;
    Params P;
    // metadata order: embeds, W_ix, W_ih, b_i, W_fx, W_fh, b_f, W_gx, W_gh, b_g, W_ox, W_oh, b_o
    const float* embeds = (const float*)d_in[0];
    P.Wx[0] = (const float*)d_in[1];  P.Wh[0] = (const float*)d_in[2];  P.b[0] = (const float*)d_in[3];
    P.Wx[1] = (const float*)d_in[4];  P.Wh[1] = (const float*)d_in[5];  P.b[1] = (const float*)d_in[6];
    P.Wx[2] = (const float*)d_in[7];  P.Wh[2] = (const float*)d_in[8];  P.b[2] = (const float*)d_in[9];
    P.Wx[3] = (const float*)d_in[10]; P.Wh[3] = (const float*)d_in[11]; P.b[3] = (const float*)d_in[12];
    P.out = (float*)d_out;

    cudaFuncSetAttribute(lstm_kernel, cudaFuncAttributeMaxDynamicSharedMemorySize, SMEM_TOTAL);

    setup_kernel<<<1, NTHREADS>>>();
    convX_kernel<<<(TSTEPS * NBATCH * EMB) / 4 / NTHREADS, NTHREADS>>>(embeds);
    lstm_kernel<<<CTAS, NTHREADS, SMEM_TOTAL>>>(P);
}